// round 16
// baseline (speedup 1.0000x reference)
#include <cuda_runtime.h>
#include <cuda_fp16.h>
#include <cuda_bf16.h>

// Problem constants (fixed shapes for this problem)
#define NN  40000
#define DD  128
#define EE  640000
#define CAP 64          // padded CSR slots per node (deg ~ Poisson(16), max ~40)

// Scratch (device globals; no allocation allowed)
// g_cnt starts zeroed (module load) and is re-zeroed by k_aggregate each run.
__device__ __half         g_y[NN * DD];       // relu(x @ W^T + b), fp16 (L2-resident)
__device__ int            g_cnt[NN];          // per-dst fill counters (self-zeroing)
__device__ unsigned short g_slots[NN * CAP];  // padded CSR: src ids (fit in u16), 5.1 MB

// ---------------------------------------------------------------------------
// tf32 m16n8k8 mma wrapper
// ---------------------------------------------------------------------------
static __device__ __forceinline__ void mma_tf32(
    float* c, const unsigned* a, unsigned b0, unsigned b1)
{
    asm volatile(
        "mma.sync.aligned.m16n8k8.row.col.f32.tf32.tf32.f32 "
        "{%0,%1,%2,%3}, {%4,%5,%6,%7}, {%8,%9}, {%0,%1,%2,%3};"
        : "+f"(c[0]), "+f"(c[1]), "+f"(c[2]), "+f"(c[3])
        : "r"(a[0]), "r"(a[1]), "r"(a[2]), "r"(a[3]), "r"(b0), "r"(b1));
}

static __device__ __forceinline__ unsigned f2tf32(float v) {
    unsigned u;
    asm("cvt.rna.tf32.f32 %0, %1;" : "=r"(u) : "f"(v));
    return u;
}

// ---------------------------------------------------------------------------
// Kernel 1: y = relu(x @ W^T + b) via tf32 tensor cores, fp16 output.
// Chunked form (36 KB smem -> multiple CTAs/SM, natural cross-CTA overlap).
// Block tile 128x128, 8 warps as 4(m) x 2(n); warp tile 32x64 = 2x8 m16n8k8.
// Smem stride 36 words: fragment LDS bank = (4*row+col)%32 -> conflict-free.
// W needs no transpose: mma .col B (k-major) == W row-major [n][k].
// ---------------------------------------------------------------------------
__global__ __launch_bounds__(256) void k_gemm_relu(
    const float* __restrict__ x, const float* __restrict__ W,
    const float* __restrict__ b)
{
    __shared__ float xs[128][36];    // A tile: x rows (tf32 bits)
    __shared__ float ws[128][36];    // B tile: W rows (tf32 bits)

    const int t      = threadIdx.x;
    const int lane   = t & 31;
    const int wid    = t >> 5;
    const int warp_m = wid & 3;      // 0..3 -> 32 rows each
    const int warp_n = wid >> 2;     // 0..1 -> 64 cols each
    const int row0   = blockIdx.x * 128;
    const int grp    = lane >> 2;    // 0..7
    const int tig    = lane & 3;     // 0..3

    float acc[2][8][4];
#pragma unroll
    for (int mt = 0; mt < 2; mt++)
#pragma unroll
        for (int nt = 0; nt < 8; nt++)
#pragma unroll
            for (int k = 0; k < 4; k++) acc[mt][nt][k] = 0.f;

    for (int kc = 0; kc < DD; kc += 32) {
        // load x + W tiles: 128 rows x 8 float4 each; 4 float4 per thread each
#pragma unroll
        for (int p = 0; p < 4; p++) {
            int i = t + p * 256;
            int r = i >> 3, c = i & 7;
            int gr = row0 + r; gr = gr < NN ? gr : NN - 1;
            float4 v = ((const float4*)x)[gr * 32 + (kc >> 2) + c];
            v.x = __uint_as_float(f2tf32(v.x));
            v.y = __uint_as_float(f2tf32(v.y));
            v.z = __uint_as_float(f2tf32(v.z));
            v.w = __uint_as_float(f2tf32(v.w));
            *(float4*)&xs[r][c * 4] = v;

            float4 w = ((const float4*)W)[r * 32 + (kc >> 2) + c];
            w.x = __uint_as_float(f2tf32(w.x));
            w.y = __uint_as_float(f2tf32(w.y));
            w.z = __uint_as_float(f2tf32(w.z));
            w.w = __uint_as_float(f2tf32(w.w));
            *(float4*)&ws[r][c * 4] = w;
        }
        __syncthreads();

#pragma unroll
        for (int ks = 0; ks < 4; ks++) {
            const int kb = ks * 8;
            unsigned a[2][4];
#pragma unroll
            for (int mt = 0; mt < 2; mt++) {
                int ar = warp_m * 32 + mt * 16 + grp;
                a[mt][0] = __float_as_uint(xs[ar    ][kb + tig]);
                a[mt][1] = __float_as_uint(xs[ar + 8][kb + tig]);
                a[mt][2] = __float_as_uint(xs[ar    ][kb + tig + 4]);
                a[mt][3] = __float_as_uint(xs[ar + 8][kb + tig + 4]);
            }
#pragma unroll
            for (int nt = 0; nt < 8; nt++) {
                int bc = warp_n * 64 + nt * 8 + grp;
                unsigned b0 = __float_as_uint(ws[bc][kb + tig]);
                unsigned b1 = __float_as_uint(ws[bc][kb + tig + 4]);
                mma_tf32(acc[0][nt], a[0], b0, b1);
                mma_tf32(acc[1][nt], a[1], b0, b1);
            }
        }
        __syncthreads();
    }

    // epilogue: +bias, relu, fp16 store (half2 per row per n-tile)
#pragma unroll
    for (int nt = 0; nt < 8; nt++) {
        int col = warp_n * 64 + nt * 8 + tig * 2;
        float2 bb = *(const float2*)&b[col];
#pragma unroll
        for (int mt = 0; mt < 2; mt++) {
            int r0 = row0 + warp_m * 32 + mt * 16 + grp;
            int r1 = r0 + 8;
            if (r0 < NN) {
                __half2 v = __floats2half2_rn(
                    fmaxf(acc[mt][nt][0] + bb.x, 0.f),
                    fmaxf(acc[mt][nt][1] + bb.y, 0.f));
                *(__half2*)&g_y[r0 * DD + col] = v;
            }
            if (r1 < NN) {
                __half2 v = __floats2half2_rn(
                    fmaxf(acc[mt][nt][2] + bb.x, 0.f),
                    fmaxf(acc[mt][nt][3] + bb.y, 0.f));
                *(__half2*)&g_y[r1 * DD + col] = v;
            }
        }
    }
}

// ---------------------------------------------------------------------------
// Kernel 2: one-pass scatter into padded CSR (2 edges per thread via int4).
// Counters arrive zeroed (module load / previous aggregate run).
// Slot order within a node is nondeterministic; max is order-invariant.
// ---------------------------------------------------------------------------
__global__ void k_scatter(const int4* __restrict__ e2, int ne2) {
    int i = blockIdx.x * blockDim.x + threadIdx.x;
    if (i < ne2) {
        int4 p = e2[i];   // (src0, dst0, src1, dst1)
        int pos0 = atomicAdd(&g_cnt[p.y], 1);
        int pos1 = atomicAdd(&g_cnt[p.w], 1);
        if (pos0 < CAP) g_slots[p.y * CAP + pos0] = (unsigned short)p.x;
        if (pos1 < CAP) g_slots[p.w * CAP + pos1] = (unsigned short)p.z;
    }
}

// ---------------------------------------------------------------------------
// Kernel 3: per-dst gather-max over fp16 y + residual + RMSNorm. Warp/node.
// (round-10 loop body -- every restructure attempt regressed)
// Self-zeros g_cnt[node] after reading, removing the zeroing kernel from the
// next run's critical path.
// ---------------------------------------------------------------------------
__global__ __launch_bounds__(256) void k_aggregate(
    const float* __restrict__ x, const float* __restrict__ g,
    const float* __restrict__ rb, float* __restrict__ out, int n)
{
    const int node = (blockIdx.x * blockDim.x + threadIdx.x) >> 5;
    const int lane = threadIdx.x & 31;
    if (node >= n) return;

    // prefetch residual row (independent of the cnt/slot chain)
    float4 xv = ((const float4*)x)[node * 32 + lane];

    int cnt = g_cnt[node];
    if (lane == 0) g_cnt[node] = 0;        // self-zero for the next launch
    cnt = cnt < CAP ? cnt : CAP;
    const int start = node * CAP;
    const uint2* yv = (const uint2*)g_y;   // 8B per lane per row

    __half2 m0 = __float2half2_rn(0.f);
    __half2 m1 = __float2half2_rn(0.f);

    int j = 0;
    for (; j + 8 <= cnt; j += 8) {
        int s0 = g_slots[start + j];
        int s1 = g_slots[start + j + 1];
        int s2 = g_slots[start + j + 2];
        int s3 = g_slots[start + j + 3];
        int s4 = g_slots[start + j + 4];
        int s5 = g_slots[start + j + 5];
        int s6 = g_slots[start + j + 6];
        int s7 = g_slots[start + j + 7];
        uint2 v0 = yv[s0 * 32 + lane];
        uint2 v1 = yv[s1 * 32 + lane];
        uint2 v2 = yv[s2 * 32 + lane];
        uint2 v3 = yv[s3 * 32 + lane];
        uint2 v4 = yv[s4 * 32 + lane];
        uint2 v5 = yv[s5 * 32 + lane];
        uint2 v6 = yv[s6 * 32 + lane];
        uint2 v7 = yv[s7 * 32 + lane];
        m0 = __hmax2(m0, __hmax2(
                 __hmax2(__hmax2(*(__half2*)&v0.x, *(__half2*)&v1.x),
                         __hmax2(*(__half2*)&v2.x, *(__half2*)&v3.x)),
                 __hmax2(__hmax2(*(__half2*)&v4.x, *(__half2*)&v5.x),
                         __hmax2(*(__half2*)&v6.x, *(__half2*)&v7.x))));
        m1 = __hmax2(m1, __hmax2(
                 __hmax2(__hmax2(*(__half2*)&v0.y, *(__half2*)&v1.y),
                         __hmax2(*(__half2*)&v2.y, *(__half2*)&v3.y)),
                 __hmax2(__hmax2(*(__half2*)&v4.y, *(__half2*)&v5.y),
                         __hmax2(*(__half2*)&v6.y, *(__half2*)&v7.y))));
    }
    for (; j + 4 <= cnt; j += 4) {
        int s0 = g_slots[start + j];
        int s1 = g_slots[start + j + 1];
        int s2 = g_slots[start + j + 2];
        int s3 = g_slots[start + j + 3];
        uint2 v0 = yv[s0 * 32 + lane];
        uint2 v1 = yv[s1 * 32 + lane];
        uint2 v2 = yv[s2 * 32 + lane];
        uint2 v3 = yv[s3 * 32 + lane];
        m0 = __hmax2(m0, __hmax2(__hmax2(*(__half2*)&v0.x, *(__half2*)&v1.x),
                                 __hmax2(*(__half2*)&v2.x, *(__half2*)&v3.x)));
        m1 = __hmax2(m1, __hmax2(__hmax2(*(__half2*)&v0.y, *(__half2*)&v1.y),
                                 __hmax2(*(__half2*)&v2.y, *(__half2*)&v3.y)));
    }
    for (; j < cnt; j++) {
        int s = g_slots[start + j];
        uint2 v = yv[s * 32 + lane];
        m0 = __hmax2(m0, *(__half2*)&v.x);
        m1 = __hmax2(m1, *(__half2*)&v.y);
    }

    float2 f0 = __half22float2(m0);
    float2 f1 = __half22float2(m1);

    float4 h;
    h.x = xv.x + f0.x; h.y = xv.y + f0.y;
    h.z = xv.z + f1.x; h.w = xv.w + f1.y;

    float ss = h.x * h.x + h.y * h.y + h.z * h.z + h.w * h.w;
#pragma unroll
    for (int d = 16; d; d >>= 1) ss += __shfl_xor_sync(0xFFFFFFFFu, ss, d);

    float inv = rsqrtf(ss * (1.0f / DD) + 1e-5f);

    float4 gv = ((const float4*)g)[lane];
    float4 rv = ((const float4*)rb)[lane];
    float4 o;
    o.x = h.x * inv * gv.x + rv.x;
    o.y = h.y * inv * gv.y + rv.y;
    o.z = h.z * inv * gv.z + rv.z;
    o.w = h.w * inv * gv.w + rv.w;
    ((float4*)out)[node * 32 + lane] = o;
}

// ---------------------------------------------------------------------------
// Launch: scatter on a second stream, concurrent with GEMM. No zeroing
// kernel: counters are zeroed by the previous aggregate (or module load).
// ---------------------------------------------------------------------------
extern "C" void kernel_launch(void* const* d_in, const int* in_sizes, int n_in,
                              void* d_out, int out_size)
{
    const float* x  = (const float*)d_in[0];
    const int4*  e2 = (const int4*) d_in[1];
    const float* W  = (const float*)d_in[2];
    const float* b  = (const float*)d_in[3];
    const float* g  = (const float*)d_in[4];
    const float* rb = (const float*)d_in[5];
    float* out = (float*)d_out;

    const int n   = in_sizes[0] / DD;   // 40000
    const int ne  = in_sizes[1] / 2;    // 640000
    const int ne2 = ne / 2;             // 320000 int4 packets

    cudaStream_t sB;
    cudaEvent_t  eFork, eJoin;
    cudaStreamCreateWithFlags(&sB, cudaStreamNonBlocking);
    cudaEventCreateWithFlags(&eFork, cudaEventDisableTiming);
    cudaEventCreateWithFlags(&eJoin, cudaEventDisableTiming);

    // fork from the (captured) main stream
    cudaEventRecord(eFork, (cudaStream_t)0);
    cudaStreamWaitEvent(sB, eFork, 0);

    // stream B: padded-CSR scatter (depends only on e)
    k_scatter<<<(ne2 + 255) / 256, 256, 0, sB>>>(e2, ne2);
    cudaEventRecord(eJoin, sB);

    // main stream: tf32 tensor-core GEMM (depends only on x, W, b)
    k_gemm_relu<<<(n + 127) / 128, 256>>>(x, W, b);

    // join, then aggregate (also re-zeros g_cnt for the next replay)
    cudaStreamWaitEvent((cudaStream_t)0, eJoin, 0);
    k_aggregate<<<(n * 32 + 255) / 256, 256>>>(x, g, rb, out, n);
}

// round 17
// speedup vs baseline: 1.6418x; 1.6418x over previous
#include <cuda_runtime.h>
#include <cuda_fp16.h>
#include <cuda_bf16.h>

// Problem constants (fixed shapes for this problem)
#define NN  40000
#define DD  128
#define EE  640000
#define CAP 64          // padded CSR slots per node (deg ~ Poisson(16), max ~40)

// Scratch (device globals; no allocation allowed)
__device__ __half         g_y[NN * DD];       // relu(x @ W^T + b), fp16 (L2-resident)
__device__ int            g_cnt[NN];          // per-dst fill counters
__device__ unsigned short g_slots[NN * CAP];  // padded CSR: src ids (fit in u16), 5.1 MB

// ---------------------------------------------------------------------------
// Kernel 1: zero fill counters (vectorized)
// ---------------------------------------------------------------------------
__global__ void k_zero_cnt(int n4) {
    int i = blockIdx.x * blockDim.x + threadIdx.x;
    if (i < n4) ((int4*)g_cnt)[i] = make_int4(0, 0, 0, 0);
}

// ---------------------------------------------------------------------------
// tf32 m16n8k8 mma wrapper
// ---------------------------------------------------------------------------
static __device__ __forceinline__ void mma_tf32(
    float* c, const unsigned* a, unsigned b0, unsigned b1)
{
    asm volatile(
        "mma.sync.aligned.m16n8k8.row.col.f32.tf32.tf32.f32 "
        "{%0,%1,%2,%3}, {%4,%5,%6,%7}, {%8,%9}, {%0,%1,%2,%3};"
        : "+f"(c[0]), "+f"(c[1]), "+f"(c[2]), "+f"(c[3])
        : "r"(a[0]), "r"(a[1]), "r"(a[2]), "r"(a[3]), "r"(b0), "r"(b1));
}

static __device__ __forceinline__ unsigned f2tf32(float v) {
    unsigned u;
    asm("cvt.rna.tf32.f32 %0, %1;" : "=r"(u) : "f"(v));
    return u;
}

// ---------------------------------------------------------------------------
// Kernel 2: y = relu(x @ W^T + b) via tf32 tensor cores, fp16 output.
// Chunked form (36 KB smem -> multiple CTAs/SM, natural cross-CTA overlap).
// Block tile 128x128, 8 warps as 4(m) x 2(n); warp tile 32x64 = 2x8 m16n8k8.
// Smem stride 36 words: fragment LDS bank = (4*row+col)%32 -> conflict-free.
// W needs no transpose: mma .col B (k-major) == W row-major [n][k].
// ---------------------------------------------------------------------------
__global__ __launch_bounds__(256) void k_gemm_relu(
    const float* __restrict__ x, const float* __restrict__ W,
    const float* __restrict__ b)
{
    __shared__ float xs[128][36];    // A tile: x rows (tf32 bits)
    __shared__ float ws[128][36];    // B tile: W rows (tf32 bits)

    const int t      = threadIdx.x;
    const int lane   = t & 31;
    const int wid    = t >> 5;
    const int warp_m = wid & 3;      // 0..3 -> 32 rows each
    const int warp_n = wid >> 2;     // 0..1 -> 64 cols each
    const int row0   = blockIdx.x * 128;
    const int grp    = lane >> 2;    // 0..7
    const int tig    = lane & 3;     // 0..3

    float acc[2][8][4];
#pragma unroll
    for (int mt = 0; mt < 2; mt++)
#pragma unroll
        for (int nt = 0; nt < 8; nt++)
#pragma unroll
            for (int k = 0; k < 4; k++) acc[mt][nt][k] = 0.f;

    for (int kc = 0; kc < DD; kc += 32) {
        // load x + W tiles: 128 rows x 8 float4 each; 4 float4 per thread each
#pragma unroll
        for (int p = 0; p < 4; p++) {
            int i = t + p * 256;
            int r = i >> 3, c = i & 7;
            int gr = row0 + r; gr = gr < NN ? gr : NN - 1;
            float4 v = ((const float4*)x)[gr * 32 + (kc >> 2) + c];
            v.x = __uint_as_float(f2tf32(v.x));
            v.y = __uint_as_float(f2tf32(v.y));
            v.z = __uint_as_float(f2tf32(v.z));
            v.w = __uint_as_float(f2tf32(v.w));
            *(float4*)&xs[r][c * 4] = v;

            float4 w = ((const float4*)W)[r * 32 + (kc >> 2) + c];
            w.x = __uint_as_float(f2tf32(w.x));
            w.y = __uint_as_float(f2tf32(w.y));
            w.z = __uint_as_float(f2tf32(w.z));
            w.w = __uint_as_float(f2tf32(w.w));
            *(float4*)&ws[r][c * 4] = w;
        }
        __syncthreads();

#pragma unroll
        for (int ks = 0; ks < 4; ks++) {
            const int kb = ks * 8;
            unsigned a[2][4];
#pragma unroll
            for (int mt = 0; mt < 2; mt++) {
                int ar = warp_m * 32 + mt * 16 + grp;
                a[mt][0] = __float_as_uint(xs[ar    ][kb + tig]);
                a[mt][1] = __float_as_uint(xs[ar + 8][kb + tig]);
                a[mt][2] = __float_as_uint(xs[ar    ][kb + tig + 4]);
                a[mt][3] = __float_as_uint(xs[ar + 8][kb + tig + 4]);
            }
#pragma unroll
            for (int nt = 0; nt < 8; nt++) {
                int bc = warp_n * 64 + nt * 8 + grp;
                unsigned b0 = __float_as_uint(ws[bc][kb + tig]);
                unsigned b1 = __float_as_uint(ws[bc][kb + tig + 4]);
                mma_tf32(acc[0][nt], a[0], b0, b1);
                mma_tf32(acc[1][nt], a[1], b0, b1);
            }
        }
        __syncthreads();
    }

    // epilogue: +bias, relu, fp16 store (half2 per row per n-tile)
#pragma unroll
    for (int nt = 0; nt < 8; nt++) {
        int col = warp_n * 64 + nt * 8 + tig * 2;
        float2 bb = *(const float2*)&b[col];
#pragma unroll
        for (int mt = 0; mt < 2; mt++) {
            int r0 = row0 + warp_m * 32 + mt * 16 + grp;
            int r1 = r0 + 8;
            if (r0 < NN) {
                __half2 v = __floats2half2_rn(
                    fmaxf(acc[mt][nt][0] + bb.x, 0.f),
                    fmaxf(acc[mt][nt][1] + bb.y, 0.f));
                *(__half2*)&g_y[r0 * DD + col] = v;
            }
            if (r1 < NN) {
                __half2 v = __floats2half2_rn(
                    fmaxf(acc[mt][nt][2] + bb.x, 0.f),
                    fmaxf(acc[mt][nt][3] + bb.y, 0.f));
                *(__half2*)&g_y[r1 * DD + col] = v;
            }
        }
    }
}

// ---------------------------------------------------------------------------
// Kernel 3: one-pass scatter into padded CSR. ONE edge per thread (int2
// coalesced loads) -- maximum warp count, one outstanding ATOMG per thread,
// best coverage of the ~318-cyc L2-atomic latency.
// Slot order within a node is nondeterministic; max is order-invariant.
// ---------------------------------------------------------------------------
__global__ void k_scatter(const int2* __restrict__ e, int ne) {
    int i = blockIdx.x * blockDim.x + threadIdx.x;
    if (i < ne) {
        int2 p = e[i];   // (src, dst)
        int pos = atomicAdd(&g_cnt[p.y], 1);
        if (pos < CAP) g_slots[p.y * CAP + pos] = (unsigned short)p.x;
    }
}

// ---------------------------------------------------------------------------
// Kernel 4: per-dst gather-max over fp16 y + residual + RMSNorm. Warp/node.
// (exact round-15 structure -- every restructure attempt regressed)
// ---------------------------------------------------------------------------
__global__ __launch_bounds__(256) void k_aggregate(
    const float* __restrict__ x, const float* __restrict__ g,
    const float* __restrict__ rb, float* __restrict__ out, int n)
{
    const int node = (blockIdx.x * blockDim.x + threadIdx.x) >> 5;
    const int lane = threadIdx.x & 31;
    if (node >= n) return;

    int cnt = g_cnt[node];
    cnt = cnt < CAP ? cnt : CAP;
    const int start = node * CAP;
    const uint2* yv = (const uint2*)g_y;   // 8B per lane per row

    __half2 m0 = __float2half2_rn(0.f);
    __half2 m1 = __float2half2_rn(0.f);

    int j = 0;
    for (; j + 8 <= cnt; j += 8) {
        int s0 = g_slots[start + j];
        int s1 = g_slots[start + j + 1];
        int s2 = g_slots[start + j + 2];
        int s3 = g_slots[start + j + 3];
        int s4 = g_slots[start + j + 4];
        int s5 = g_slots[start + j + 5];
        int s6 = g_slots[start + j + 6];
        int s7 = g_slots[start + j + 7];
        uint2 v0 = yv[s0 * 32 + lane];
        uint2 v1 = yv[s1 * 32 + lane];
        uint2 v2 = yv[s2 * 32 + lane];
        uint2 v3 = yv[s3 * 32 + lane];
        uint2 v4 = yv[s4 * 32 + lane];
        uint2 v5 = yv[s5 * 32 + lane];
        uint2 v6 = yv[s6 * 32 + lane];
        uint2 v7 = yv[s7 * 32 + lane];
        m0 = __hmax2(m0, __hmax2(
                 __hmax2(__hmax2(*(__half2*)&v0.x, *(__half2*)&v1.x),
                         __hmax2(*(__half2*)&v2.x, *(__half2*)&v3.x)),
                 __hmax2(__hmax2(*(__half2*)&v4.x, *(__half2*)&v5.x),
                         __hmax2(*(__half2*)&v6.x, *(__half2*)&v7.x))));
        m1 = __hmax2(m1, __hmax2(
                 __hmax2(__hmax2(*(__half2*)&v0.y, *(__half2*)&v1.y),
                         __hmax2(*(__half2*)&v2.y, *(__half2*)&v3.y)),
                 __hmax2(__hmax2(*(__half2*)&v4.y, *(__half2*)&v5.y),
                         __hmax2(*(__half2*)&v6.y, *(__half2*)&v7.y))));
    }
    for (; j + 4 <= cnt; j += 4) {
        int s0 = g_slots[start + j];
        int s1 = g_slots[start + j + 1];
        int s2 = g_slots[start + j + 2];
        int s3 = g_slots[start + j + 3];
        uint2 v0 = yv[s0 * 32 + lane];
        uint2 v1 = yv[s1 * 32 + lane];
        uint2 v2 = yv[s2 * 32 + lane];
        uint2 v3 = yv[s3 * 32 + lane];
        m0 = __hmax2(m0, __hmax2(__hmax2(*(__half2*)&v0.x, *(__half2*)&v1.x),
                                 __hmax2(*(__half2*)&v2.x, *(__half2*)&v3.x)));
        m1 = __hmax2(m1, __hmax2(__hmax2(*(__half2*)&v0.y, *(__half2*)&v1.y),
                                 __hmax2(*(__half2*)&v2.y, *(__half2*)&v3.y)));
    }
    for (; j < cnt; j++) {
        int s = g_slots[start + j];
        uint2 v = yv[s * 32 + lane];
        m0 = __hmax2(m0, *(__half2*)&v.x);
        m1 = __hmax2(m1, *(__half2*)&v.y);
    }

    float2 f0 = __half22float2(m0);
    float2 f1 = __half22float2(m1);

    float4 xv = ((const float4*)x)[node * 32 + lane];
    float4 h;
    h.x = xv.x + f0.x; h.y = xv.y + f0.y;
    h.z = xv.z + f1.x; h.w = xv.w + f1.y;

    float ss = h.x * h.x + h.y * h.y + h.z * h.z + h.w * h.w;
#pragma unroll
    for (int d = 16; d; d >>= 1) ss += __shfl_xor_sync(0xFFFFFFFFu, ss, d);

    float inv = rsqrtf(ss * (1.0f / DD) + 1e-5f);

    float4 gv = ((const float4*)g)[lane];
    float4 rv = ((const float4*)rb)[lane];
    float4 o;
    o.x = h.x * inv * gv.x + rv.x;
    o.y = h.y * inv * gv.y + rv.y;
    o.z = h.z * inv * gv.z + rv.z;
    o.w = h.w * inv * gv.w + rv.w;
    ((float4*)out)[node * 32 + lane] = o;
}

// ---------------------------------------------------------------------------
// Launch: CSR build chain on a second stream, concurrent with GEMM.
// ---------------------------------------------------------------------------
extern "C" void kernel_launch(void* const* d_in, const int* in_sizes, int n_in,
                              void* d_out, int out_size)
{
    const float* x  = (const float*)d_in[0];
    const int2*  e  = (const int2*) d_in[1];
    const float* W  = (const float*)d_in[2];
    const float* b  = (const float*)d_in[3];
    const float* g  = (const float*)d_in[4];
    const float* rb = (const float*)d_in[5];
    float* out = (float*)d_out;

    const int n  = in_sizes[0] / DD;   // 40000
    const int ne = in_sizes[1] / 2;    // 640000

    cudaStream_t sB;
    cudaEvent_t  eFork, eJoin;
    cudaStreamCreateWithFlags(&sB, cudaStreamNonBlocking);
    cudaEventCreateWithFlags(&eFork, cudaEventDisableTiming);
    cudaEventCreateWithFlags(&eJoin, cudaEventDisableTiming);

    // fork from the (captured) main stream
    cudaEventRecord(eFork, (cudaStream_t)0);
    cudaStreamWaitEvent(sB, eFork, 0);

    // stream B: padded-CSR build (depends only on e)
    k_zero_cnt<<<(n / 4 + 255) / 256, 256, 0, sB>>>(n / 4);
    k_scatter <<<(ne + 255) / 256, 256, 0, sB>>>(e, ne);
    cudaEventRecord(eJoin, sB);

    // main stream: tf32 tensor-core GEMM (depends only on x, W, b)
    k_gemm_relu<<<(n + 127) / 128, 256>>>(x, W, b);

    // join, then aggregate
    cudaStreamWaitEvent((cudaStream_t)0, eJoin, 0);
    k_aggregate<<<(n * 32 + 255) / 256, 256>>>(x, g, rb, out, n);
}